// round 3
// baseline (speedup 1.0000x reference)
#include <cuda_runtime.h>
#include <cuda_bf16.h>
#include <stdint.h>

#define B_ROWS 32768
#define D_IN   512
#define D_OUT  2048
#define VBS    256
#define NVB    128
#define EPS_BN 1e-5f

// GEMM tiling (HMMA mma.sync path; tcgen05 not available on this toolchain target)
#define TM 128
#define TN 128
#define TK 32
#define STAGES 4
#define KSTAGES (D_IN / TK)          // 16

#define TILE_B   8192                 // one 128x32 bf16 tile
#define STAGE_B  (4 * TILE_B)         // Ahi, Alo, Bhi, Blo
#define GEMM_SMEM (STAGES * STAGE_B)  // 131072

// -------- static device scratch (no cudaMalloc allowed) --------
__device__ __align__(1024) __nv_bfloat16 g_Ahi[(size_t)B_ROWS * D_IN];
__device__ __align__(1024) __nv_bfloat16 g_Alo[(size_t)B_ROWS * D_IN];
__device__ __align__(1024) __nv_bfloat16 g_Bhi[(size_t)D_OUT * D_IN];
__device__ __align__(1024) __nv_bfloat16 g_Blo[(size_t)D_OUT * D_IN];
__device__ __align__(1024) float g_X[(size_t)B_ROWS * D_OUT];
__device__ __align__(1024) float g_scale[(size_t)NVB * D_OUT];
__device__ __align__(1024) float g_shift[(size_t)NVB * D_OUT];

// -------- helpers --------
__device__ __forceinline__ uint32_t cvta_shared_u32(const void* p) {
    uint32_t r;
    asm("{ .reg .u64 t; cvta.to.shared.u64 t, %1; cvt.u32.u64 %0, t; }" : "=r"(r) : "l"(p));
    return r;
}
__device__ __forceinline__ void cp16(uint32_t dst, const void* src) {
    asm volatile("cp.async.cg.shared.global [%0], [%1], 16;" :: "r"(dst), "l"(src) : "memory");
}
__device__ __forceinline__ void cp_commit() { asm volatile("cp.async.commit_group;" ::: "memory"); }
__device__ __forceinline__ void cp_wait2()  { asm volatile("cp.async.wait_group 2;" ::: "memory"); }

__device__ __forceinline__ void ldsm_x4(uint32_t& r0, uint32_t& r1, uint32_t& r2, uint32_t& r3,
                                        uint32_t addr) {
    asm volatile("ldmatrix.sync.aligned.m8n8.x4.shared.b16 {%0,%1,%2,%3}, [%4];"
                 : "=r"(r0), "=r"(r1), "=r"(r2), "=r"(r3) : "r"(addr));
}
__device__ __forceinline__ void hmma(float* c, const uint32_t* a, const uint32_t* b) {
    asm volatile("mma.sync.aligned.m16n8k16.row.col.f32.bf16.bf16.f32 "
                 "{%0,%1,%2,%3}, {%4,%5,%6,%7}, {%8,%9}, {%0,%1,%2,%3};"
                 : "+f"(c[0]), "+f"(c[1]), "+f"(c[2]), "+f"(c[3])
                 : "r"(a[0]), "r"(a[1]), "r"(a[2]), "r"(a[3]), "r"(b[0]), "r"(b[1]));
}

// swizzled smem byte offset for (row, 16B-chunk c) of a 128x32-bf16 tile (64B rows)
// chunk period 8 rows -> conflict-free for ldmatrix phases and cp.async stores
__device__ __forceinline__ uint32_t swoff(int row, int c) {
    return (uint32_t)(row * 64 + ((c ^ ((row >> 1) & 3)) << 4));
}

// -------- fp32 -> bf16 hi/lo split --------
__device__ __forceinline__ void split_store(__nv_bfloat162* hi, __nv_bfloat162* lo,
                                            int i, float4 v) {
    __nv_bfloat16 h0 = __float2bfloat16(v.x), h1 = __float2bfloat16(v.y);
    __nv_bfloat16 h2 = __float2bfloat16(v.z), h3 = __float2bfloat16(v.w);
    float r0 = v.x - __bfloat162float(h0), r1 = v.y - __bfloat162float(h1);
    float r2 = v.z - __bfloat162float(h2), r3 = v.w - __bfloat162float(h3);
    hi[2*i+0] = __halves2bfloat162(h0, h1);
    hi[2*i+1] = __halves2bfloat162(h2, h3);
    lo[2*i+0] = __halves2bfloat162(__float2bfloat16(r0), __float2bfloat16(r1));
    lo[2*i+1] = __halves2bfloat162(__float2bfloat16(r2), __float2bfloat16(r3));
}
__global__ void convertA_kernel(const float4* __restrict__ src) {
    const int n4 = (B_ROWS * D_IN) / 4;
    __nv_bfloat162* hi = reinterpret_cast<__nv_bfloat162*>(g_Ahi);
    __nv_bfloat162* lo = reinterpret_cast<__nv_bfloat162*>(g_Alo);
    for (int i = blockIdx.x * blockDim.x + threadIdx.x; i < n4; i += gridDim.x * blockDim.x)
        split_store(hi, lo, i, src[i]);
}
__global__ void convertB_kernel(const float4* __restrict__ src) {
    const int n4 = (D_OUT * D_IN) / 4;
    __nv_bfloat162* hi = reinterpret_cast<__nv_bfloat162*>(g_Bhi);
    __nv_bfloat162* lo = reinterpret_cast<__nv_bfloat162*>(g_Blo);
    for (int i = blockIdx.x * blockDim.x + threadIdx.x; i < n4; i += gridDim.x * blockDim.x)
        split_store(hi, lo, i, src[i]);
}

// -------- GEMM: X = A(32768x512) @ B(2048x512)^T via HMMA bf16x3 --------
__device__ __forceinline__ void load_stage(uint32_t smem, int buf, int bm, int bn,
                                           int k0, int tid) {
    uint32_t base = smem + (uint32_t)buf * STAGE_B;
    #pragma unroll
    for (int i = 0; i < 2; i++) {
        int idx = tid + i * 256;           // 0..511 : 128 rows x 4 chunks
        int r = idx >> 2, c = idx & 3;
        uint32_t off = swoff(r, c);
        const __nv_bfloat16* ga = g_Ahi + (size_t)(bm * TM + r) * D_IN + k0 + c * 8;
        const __nv_bfloat16* gb = g_Bhi + (size_t)(bn * TN + r) * D_IN + k0 + c * 8;
        cp16(base + off,                ga);
        cp16(base + TILE_B + off,       ga + (g_Alo - g_Ahi));
        cp16(base + 2 * TILE_B + off,   gb);
        cp16(base + 3 * TILE_B + off,   gb + (g_Blo - g_Bhi));
    }
}

__global__ void __launch_bounds__(256, 1) gemm_kernel() {
    extern __shared__ char smraw[];
    const uint32_t smem = cvta_shared_u32(smraw);

    const int tid  = threadIdx.x;
    const int lane = tid & 31;
    const int wid  = tid >> 5;
    const int wm   = wid & 1;        // 2 warps along M
    const int wn   = wid >> 1;       // 4 warps along N
    const int bm = blockIdx.y, bn = blockIdx.x;

    // per-thread ldmatrix offsets (relative to tile base), j=0; j=1 is XOR 32
    uint32_t aOff[4], bOff[2];
    {
        int cA = lane >> 4;                       // 0/1
        #pragma unroll
        for (int mi = 0; mi < 4; mi++) {
            int rA = wm * 64 + mi * 16 + (lane & 15);
            aOff[mi] = swoff(rA, cA);
        }
        int cB = (lane >> 3) & 1;                 // 0/1
        #pragma unroll
        for (int bi = 0; bi < 2; bi++) {
            int rB = wn * 32 + bi * 16 + ((lane >> 4) << 3) + (lane & 7);
            bOff[bi] = swoff(rB, cB);
        }
    }

    float acc[4][4][4];
    #pragma unroll
    for (int mi = 0; mi < 4; mi++)
        #pragma unroll
        for (int ni = 0; ni < 4; ni++)
            #pragma unroll
            for (int k = 0; k < 4; k++) acc[mi][ni][k] = 0.f;

    // prologue: stages 0..2
    #pragma unroll
    for (int s = 0; s < STAGES - 1; s++) {
        load_stage(smem, s, bm, bn, s * TK, tid);
        cp_commit();
    }

    #pragma unroll 1
    for (int ks = 0; ks < KSTAGES; ks++) {
        cp_wait2();
        __syncthreads();

        if (ks + STAGES - 1 < KSTAGES)
            load_stage(smem, (ks + STAGES - 1) & (STAGES - 1), bm, bn,
                       (ks + STAGES - 1) * TK, tid);
        cp_commit();

        uint32_t base = smem + (uint32_t)(ks & (STAGES - 1)) * STAGE_B;

        #pragma unroll
        for (int j = 0; j < 2; j++) {
            const uint32_t jx = j << 5;     // chunk bit1 flip == byte XOR 32
            uint32_t ahi[4][4], alo[4][4], bhi[4][2], blo[4][2];
            #pragma unroll
            for (int mi = 0; mi < 4; mi++) {
                uint32_t ad = base + (aOff[mi] ^ jx);
                ldsm_x4(ahi[mi][0], ahi[mi][1], ahi[mi][2], ahi[mi][3], ad);
                ldsm_x4(alo[mi][0], alo[mi][1], alo[mi][2], alo[mi][3], ad + TILE_B);
            }
            #pragma unroll
            for (int bi = 0; bi < 2; bi++) {
                uint32_t bd = base + 2 * TILE_B + (bOff[bi] ^ jx);
                uint32_t r0, r1, r2, r3;
                ldsm_x4(r0, r1, r2, r3, bd);
                bhi[2*bi][0] = r0; bhi[2*bi][1] = r1;
                bhi[2*bi+1][0] = r2; bhi[2*bi+1][1] = r3;
                ldsm_x4(r0, r1, r2, r3, bd + TILE_B);
                blo[2*bi][0] = r0; blo[2*bi][1] = r1;
                blo[2*bi+1][0] = r2; blo[2*bi+1][1] = r3;
            }
            #pragma unroll
            for (int mi = 0; mi < 4; mi++)
                #pragma unroll
                for (int ni = 0; ni < 4; ni++) {
                    hmma(acc[mi][ni], ahi[mi], bhi[ni]);
                    hmma(acc[mi][ni], ahi[mi], blo[ni]);
                    hmma(acc[mi][ni], alo[mi], bhi[ni]);
                }
        }
        __syncthreads();
    }

    // epilogue: write 128x128 fp32 tile
    const int rbase = bm * TM + wm * 64 + (lane >> 2);
    const int cbase = bn * TN + wn * 32 + (lane & 3) * 2;
    #pragma unroll
    for (int mi = 0; mi < 4; mi++) {
        #pragma unroll
        for (int ni = 0; ni < 4; ni++) {
            float* p0 = g_X + (size_t)(rbase + mi * 16) * D_OUT + cbase + ni * 8;
            float* p1 = p0 + 8 * D_OUT;
            reinterpret_cast<float2*>(p0)[0] = make_float2(acc[mi][ni][0], acc[mi][ni][1]);
            reinterpret_cast<float2*>(p1)[0] = make_float2(acc[mi][ni][2], acc[mi][ni][3]);
        }
    }
}

// -------- GhostBN stats: per (vb, col) scale/shift --------
__global__ void stats_kernel(const float* __restrict__ gamma, const float* __restrict__ beta) {
    const int col = blockIdx.x * 256 + threadIdx.x;
    const int vb  = blockIdx.y;
    const float* __restrict__ xp = g_X + (size_t)vb * VBS * D_OUT + col;
    float s = 0.f, s2 = 0.f;
    #pragma unroll 8
    for (int r = 0; r < VBS; r++) {
        float v = xp[(size_t)r * D_OUT];
        s += v; s2 += v * v;
    }
    float mean = s * (1.0f / VBS);
    float var  = fmaxf(s2 * (1.0f / VBS) - mean * mean, 0.f);
    float sc   = gamma[col] * rsqrtf(var + EPS_BN);
    g_scale[(size_t)vb * D_OUT + col] = sc;
    g_shift[(size_t)vb * D_OUT + col] = beta[col] - mean * sc;
}

// -------- fused BN-apply * priors + sparsemax (Michelot fixed point) --------
__device__ __forceinline__ void block_red(float& s, int& c, float* ssum, int* scnt, int tid) {
    #pragma unroll
    for (int o = 16; o; o >>= 1) {
        s += __shfl_down_sync(0xFFFFFFFFu, s, o);
        c += __shfl_down_sync(0xFFFFFFFFu, c, o);
    }
    if ((tid & 31) == 0) { ssum[tid >> 5] = s; scnt[tid >> 5] = c; }
    __syncthreads();
    if (tid < 8) {
        s = ssum[tid]; c = scnt[tid];
        #pragma unroll
        for (int o = 4; o; o >>= 1) {
            s += __shfl_down_sync(0xFFu, s, o);
            c += __shfl_down_sync(0xFFu, c, o);
        }
        if (tid == 0) { ssum[0] = s; scnt[0] = c; }
    }
    __syncthreads();
    s = ssum[0]; c = scnt[0];
    __syncthreads();
}

__global__ void __launch_bounds__(256) sparsemax_kernel(const float* __restrict__ priors,
                                                        float* __restrict__ out) {
    __shared__ float ssum[8];
    __shared__ int scnt[8];
    const int row = blockIdx.x;
    const int vb  = row >> 8;
    const int tid = threadIdx.x;
    const int c0  = tid * 8;

    const float4* xr = reinterpret_cast<const float4*>(g_X + (size_t)row * D_OUT + c0);
    const float4* pr = reinterpret_cast<const float4*>(priors + (size_t)row * D_OUT + c0);
    const float4* sr = reinterpret_cast<const float4*>(g_scale + (size_t)vb * D_OUT + c0);
    const float4* hr = reinterpret_cast<const float4*>(g_shift + (size_t)vb * D_OUT + c0);

    float z[8];
    {
        float4 x0 = xr[0], x1 = xr[1], p0 = pr[0], p1 = pr[1];
        float4 s0 = sr[0], s1 = sr[1], h0 = hr[0], h1 = hr[1];
        z[0] = fmaf(x0.x, s0.x, h0.x) * p0.x;
        z[1] = fmaf(x0.y, s0.y, h0.y) * p0.y;
        z[2] = fmaf(x0.z, s0.z, h0.z) * p0.z;
        z[3] = fmaf(x0.w, s0.w, h0.w) * p0.w;
        z[4] = fmaf(x1.x, s1.x, h1.x) * p1.x;
        z[5] = fmaf(x1.y, s1.y, h1.y) * p1.y;
        z[6] = fmaf(x1.z, s1.z, h1.z) * p1.z;
        z[7] = fmaf(x1.w, s1.w, h1.w) * p1.w;
    }

    float s = 0.f; int c = 0;
    #pragma unroll
    for (int i = 0; i < 8; i++) s += z[i];
    block_red(s, c, ssum, scnt, tid);
    float tau = (s - 1.0f) * (1.0f / D_OUT);
    int prev = D_OUT;

    #pragma unroll 1
    for (int it = 0; it < 64; it++) {
        s = 0.f; c = 0;
        #pragma unroll
        for (int i = 0; i < 8; i++)
            if (z[i] > tau) { s += z[i]; c++; }
        block_red(s, c, ssum, scnt, tid);
        if (c == prev) break;
        tau = (s - 1.0f) / (float)c;
        prev = c;
    }

    float4 o0, o1;
    o0.x = fmaxf(z[0] - tau, 0.f); o0.y = fmaxf(z[1] - tau, 0.f);
    o0.z = fmaxf(z[2] - tau, 0.f); o0.w = fmaxf(z[3] - tau, 0.f);
    o1.x = fmaxf(z[4] - tau, 0.f); o1.y = fmaxf(z[5] - tau, 0.f);
    o1.z = fmaxf(z[6] - tau, 0.f); o1.w = fmaxf(z[7] - tau, 0.f);
    float4* op = reinterpret_cast<float4*>(out + (size_t)row * D_OUT + c0);
    op[0] = o0; op[1] = o1;
}

// -------- launch --------
extern "C" void kernel_launch(void* const* d_in, const int* in_sizes, int n_in,
                              void* d_out, int out_size) {
    (void)in_sizes; (void)n_in; (void)out_size;
    const float* priors = (const float*)d_in[0];
    const float* feat   = (const float*)d_in[1];
    const float* W      = (const float*)d_in[2];
    const float* gamma  = (const float*)d_in[3];
    const float* beta   = (const float*)d_in[4];

    cudaFuncSetAttribute(gemm_kernel, cudaFuncAttributeMaxDynamicSharedMemorySize, GEMM_SMEM);

    convertA_kernel<<<4096, 256>>>((const float4*)feat);
    convertB_kernel<<<512, 256>>>((const float4*)W);
    gemm_kernel<<<dim3(D_OUT / TN, B_ROWS / TM), 256, GEMM_SMEM>>>();
    stats_kernel<<<dim3(D_OUT / 256, NVB), 256>>>(gamma, beta);
    sparsemax_kernel<<<B_ROWS, 256>>>(priors, (float*)d_out);
}

// round 4
// speedup vs baseline: 1.1525x; 1.1525x over previous
#include <cuda_runtime.h>
#include <cuda_bf16.h>
#include <stdint.h>

#define B_ROWS 32768
#define D_IN   512
#define D_OUT  2048
#define VBS    256
#define NVB    128
#define EPS_BN 1e-5f

// GEMM tiling (HMMA mma.sync path; tcgen05 not supported by this toolchain target)
#define TM 128
#define TN 128
#define TK 32
#define STAGES 3
#define KSTAGES (D_IN / TK)           // 16

#define TILE_B   8192                 // one 128x32 bf16 tile
#define STAGE_B  (4 * TILE_B)         // Ahi, Alo, Bhi, Blo
#define GEMM_SMEM (STAGES * STAGE_B)  // 98304 -> 2 CTAs/SM

// -------- static device scratch (no cudaMalloc allowed) --------
__device__ __align__(1024) __nv_bfloat16 g_Ahi[(size_t)B_ROWS * D_IN];
__device__ __align__(1024) __nv_bfloat16 g_Alo[(size_t)B_ROWS * D_IN];
__device__ __align__(1024) __nv_bfloat16 g_Bhi[(size_t)D_OUT * D_IN];
__device__ __align__(1024) __nv_bfloat16 g_Blo[(size_t)D_OUT * D_IN];
__device__ __align__(1024) float g_X[(size_t)B_ROWS * D_OUT];
__device__ __align__(1024) float g_sum[(size_t)NVB * D_OUT];
__device__ __align__(1024) float g_sq[(size_t)NVB * D_OUT];
__device__ __align__(1024) float g_scale[(size_t)NVB * D_OUT];
__device__ __align__(1024) float g_shift[(size_t)NVB * D_OUT];

// -------- helpers --------
__device__ __forceinline__ uint32_t cvta_shared_u32(const void* p) {
    uint32_t r;
    asm("{ .reg .u64 t; cvta.to.shared.u64 t, %1; cvt.u32.u64 %0, t; }" : "=r"(r) : "l"(p));
    return r;
}
__device__ __forceinline__ void cp16(uint32_t dst, const void* src) {
    asm volatile("cp.async.cg.shared.global [%0], [%1], 16;" :: "r"(dst), "l"(src) : "memory");
}
__device__ __forceinline__ void cp_commit() { asm volatile("cp.async.commit_group;" ::: "memory"); }
__device__ __forceinline__ void cp_wait1()  { asm volatile("cp.async.wait_group 1;" ::: "memory"); }

__device__ __forceinline__ void ldsm_x4(uint32_t& r0, uint32_t& r1, uint32_t& r2, uint32_t& r3,
                                        uint32_t addr) {
    asm volatile("ldmatrix.sync.aligned.m8n8.x4.shared.b16 {%0,%1,%2,%3}, [%4];"
                 : "=r"(r0), "=r"(r1), "=r"(r2), "=r"(r3) : "r"(addr));
}
__device__ __forceinline__ void hmma(float* c, const uint32_t* a, const uint32_t* b) {
    asm volatile("mma.sync.aligned.m16n8k16.row.col.f32.bf16.bf16.f32 "
                 "{%0,%1,%2,%3}, {%4,%5,%6,%7}, {%8,%9}, {%0,%1,%2,%3};"
                 : "+f"(c[0]), "+f"(c[1]), "+f"(c[2]), "+f"(c[3])
                 : "r"(a[0]), "r"(a[1]), "r"(a[2]), "r"(a[3]), "r"(b[0]), "r"(b[1]));
}

// swizzled smem byte offset for (row, 16B-chunk c) of a 128x32-bf16 tile (64B rows)
__device__ __forceinline__ uint32_t swoff(int row, int c) {
    return (uint32_t)(row * 64 + ((c ^ ((row >> 1) & 3)) << 4));
}

// -------- dummy (aligns ncu capture slot onto the GEMM) --------
__global__ void dummy_kernel() {}

// -------- fp32 -> bf16 hi/lo split --------
__device__ __forceinline__ void split_store(__nv_bfloat162* hi, __nv_bfloat162* lo,
                                            int i, float4 v) {
    __nv_bfloat16 h0 = __float2bfloat16(v.x), h1 = __float2bfloat16(v.y);
    __nv_bfloat16 h2 = __float2bfloat16(v.z), h3 = __float2bfloat16(v.w);
    float r0 = v.x - __bfloat162float(h0), r1 = v.y - __bfloat162float(h1);
    float r2 = v.z - __bfloat162float(h2), r3 = v.w - __bfloat162float(h3);
    hi[2*i+0] = __halves2bfloat162(h0, h1);
    hi[2*i+1] = __halves2bfloat162(h2, h3);
    lo[2*i+0] = __halves2bfloat162(__float2bfloat16(r0), __float2bfloat16(r1));
    lo[2*i+1] = __halves2bfloat162(__float2bfloat16(r2), __float2bfloat16(r3));
}
__global__ void convertA_kernel(const float4* __restrict__ src) {
    const int n4 = (B_ROWS * D_IN) / 4;
    __nv_bfloat162* hi = reinterpret_cast<__nv_bfloat162*>(g_Ahi);
    __nv_bfloat162* lo = reinterpret_cast<__nv_bfloat162*>(g_Alo);
    for (int i = blockIdx.x * blockDim.x + threadIdx.x; i < n4; i += gridDim.x * blockDim.x)
        split_store(hi, lo, i, src[i]);
}
__global__ void convertB_kernel(const float4* __restrict__ src) {
    const int n4 = (D_OUT * D_IN) / 4;
    __nv_bfloat162* hi = reinterpret_cast<__nv_bfloat162*>(g_Bhi);
    __nv_bfloat162* lo = reinterpret_cast<__nv_bfloat162*>(g_Blo);
    int gid = blockIdx.x * blockDim.x + threadIdx.x;
    for (int i = gid; i < n4; i += gridDim.x * blockDim.x)
        split_store(hi, lo, i, src[i]);
    // zero the BN partial-sum accumulators (2 x 262144 floats, 131072 threads)
    g_sum[gid] = 0.f; g_sum[gid + 131072] = 0.f;
    g_sq[gid]  = 0.f; g_sq[gid + 131072]  = 0.f;
}

// -------- GEMM: X = A(32768x512) @ B(2048x512)^T via HMMA bf16x3, fused BN partials --------
__device__ __forceinline__ void load_stage(uint32_t smem, int buf, int bm, int bn,
                                           int k0, int tid) {
    uint32_t base = smem + (uint32_t)buf * STAGE_B;
    #pragma unroll
    for (int i = 0; i < 2; i++) {
        int idx = tid + i * 256;           // 0..511 : 128 rows x 4 chunks
        int r = idx >> 2, c = idx & 3;
        uint32_t off = swoff(r, c);
        const __nv_bfloat16* ga = g_Ahi + (size_t)(bm * TM + r) * D_IN + k0 + c * 8;
        const __nv_bfloat16* gb = g_Bhi + (size_t)(bn * TN + r) * D_IN + k0 + c * 8;
        cp16(base + off,                ga);
        cp16(base + TILE_B + off,       ga + (g_Alo - g_Ahi));
        cp16(base + 2 * TILE_B + off,   gb);
        cp16(base + 3 * TILE_B + off,   gb + (g_Blo - g_Bhi));
    }
}

__global__ void __launch_bounds__(256, 2) gemm_kernel() {
    extern __shared__ char smraw[];
    const uint32_t smem = cvta_shared_u32(smraw);

    const int tid  = threadIdx.x;
    const int lane = tid & 31;
    const int wid  = tid >> 5;
    const int wm   = wid & 1;        // 2 warps along M
    const int wn   = wid >> 1;       // 4 warps along N
    const int bm = blockIdx.y, bn = blockIdx.x;

    uint32_t aOff[4], bOff[2];
    {
        int cA = lane >> 4;
        #pragma unroll
        for (int mi = 0; mi < 4; mi++)
            aOff[mi] = swoff(wm * 64 + mi * 16 + (lane & 15), cA);
        int cB = (lane >> 3) & 1;
        #pragma unroll
        for (int bi = 0; bi < 2; bi++)
            bOff[bi] = swoff(wn * 32 + bi * 16 + ((lane >> 4) << 3) + (lane & 7), cB);
    }

    float acc[4][4][4];
    #pragma unroll
    for (int mi = 0; mi < 4; mi++)
        #pragma unroll
        for (int ni = 0; ni < 4; ni++)
            #pragma unroll
            for (int k = 0; k < 4; k++) acc[mi][ni][k] = 0.f;

    load_stage(smem, 0, bm, bn, 0, tid);  cp_commit();
    load_stage(smem, 1, bm, bn, TK, tid); cp_commit();

    #pragma unroll 1
    for (int ks = 0; ks < KSTAGES; ks++) {
        cp_wait1();
        __syncthreads();
        if (ks + 2 < KSTAGES)
            load_stage(smem, (ks + 2) % STAGES, bm, bn, (ks + 2) * TK, tid);
        cp_commit();

        uint32_t base = smem + (uint32_t)(ks % STAGES) * STAGE_B;

        #pragma unroll
        for (int j = 0; j < 2; j++) {
            const uint32_t jx = j << 5;
            uint32_t a[4][4], b[4][2], b2[4][2];
            #pragma unroll
            for (int mi = 0; mi < 4; mi++)
                ldsm_x4(a[mi][0], a[mi][1], a[mi][2], a[mi][3], base + (aOff[mi] ^ jx));
            #pragma unroll
            for (int bi = 0; bi < 2; bi++) {
                uint32_t bd = base + 2 * TILE_B + (bOff[bi] ^ jx);
                ldsm_x4(b[2*bi][0], b[2*bi][1], b[2*bi+1][0], b[2*bi+1][1], bd);
                ldsm_x4(b2[2*bi][0], b2[2*bi][1], b2[2*bi+1][0], b2[2*bi+1][1], bd + TILE_B);
            }
            // group 1: ahi * bhi  (16 independent HMMAs)
            #pragma unroll
            for (int mi = 0; mi < 4; mi++)
                #pragma unroll
                for (int ni = 0; ni < 4; ni++) hmma(acc[mi][ni], a[mi], b[ni]);
            // group 2: ahi * blo
            #pragma unroll
            for (int mi = 0; mi < 4; mi++)
                #pragma unroll
                for (int ni = 0; ni < 4; ni++) hmma(acc[mi][ni], a[mi], b2[ni]);
            // reload a := alo (reuse registers), group 3: alo * bhi
            #pragma unroll
            for (int mi = 0; mi < 4; mi++)
                ldsm_x4(a[mi][0], a[mi][1], a[mi][2], a[mi][3],
                        base + TILE_B + (aOff[mi] ^ jx));
            #pragma unroll
            for (int mi = 0; mi < 4; mi++)
                #pragma unroll
                for (int ni = 0; ni < 4; ni++) hmma(acc[mi][ni], a[mi], b[ni]);
        }
        __syncthreads();
    }

    // epilogue: write 128x128 fp32 tile + BN column partial sums
    const int rbase = bm * TM + wm * 64 + (lane >> 2);
    const int cbase = bn * TN + wn * 32 + (lane & 3) * 2;
    #pragma unroll
    for (int mi = 0; mi < 4; mi++) {
        #pragma unroll
        for (int ni = 0; ni < 4; ni++) {
            float* p0 = g_X + (size_t)(rbase + mi * 16) * D_OUT + cbase + ni * 8;
            float* p1 = p0 + 8 * D_OUT;
            reinterpret_cast<float2*>(p0)[0] = make_float2(acc[mi][ni][0], acc[mi][ni][1]);
            reinterpret_cast<float2*>(p1)[0] = make_float2(acc[mi][ni][2], acc[mi][ni][3]);
        }
    }
    // column partials over this warp's 64 rows
    const int vb = bm >> 1;
    #pragma unroll
    for (int ni = 0; ni < 4; ni++) {
        #pragma unroll
        for (int sc = 0; sc < 2; sc++) {
            float s = 0.f, q = 0.f;
            #pragma unroll
            for (int mi = 0; mi < 4; mi++) {
                float v0 = acc[mi][ni][sc], v1 = acc[mi][ni][sc + 2];
                s += v0 + v1;
                q = fmaf(v0, v0, q); q = fmaf(v1, v1, q);
            }
            #pragma unroll
            for (int off = 4; off < 32; off <<= 1) {
                s += __shfl_xor_sync(0xFFFFFFFFu, s, off);
                q += __shfl_xor_sync(0xFFFFFFFFu, q, off);
            }
            if ((lane >> 2) == 0) {
                int col = cbase + ni * 8 + sc;
                atomicAdd(&g_sum[(size_t)vb * D_OUT + col], s);
                atomicAdd(&g_sq[(size_t)vb * D_OUT + col], q);
            }
        }
    }
}

// -------- BN finalize: sums -> scale/shift --------
__global__ void finalize_kernel(const float* __restrict__ gamma, const float* __restrict__ beta) {
    const int col = blockIdx.x * 256 + threadIdx.x;
    const int vb  = blockIdx.y;
    const size_t i = (size_t)vb * D_OUT + col;
    float mean = g_sum[i] * (1.0f / VBS);
    float var  = fmaxf(g_sq[i] * (1.0f / VBS) - mean * mean, 0.f);
    float sc   = gamma[col] * rsqrtf(var + EPS_BN);
    g_scale[i] = sc;
    g_shift[i] = beta[col] - mean * sc;
}

// -------- fused BN-apply * priors + sparsemax (Michelot fixed point) --------
__device__ __forceinline__ void block_red(float& s, int& c, float* ssum, int* scnt, int tid) {
    #pragma unroll
    for (int o = 16; o; o >>= 1) {
        s += __shfl_down_sync(0xFFFFFFFFu, s, o);
        c += __shfl_down_sync(0xFFFFFFFFu, c, o);
    }
    if ((tid & 31) == 0) { ssum[tid >> 5] = s; scnt[tid >> 5] = c; }
    __syncthreads();
    if (tid < 8) {
        s = ssum[tid]; c = scnt[tid];
        #pragma unroll
        for (int o = 4; o; o >>= 1) {
            s += __shfl_down_sync(0xFFu, s, o);
            c += __shfl_down_sync(0xFFu, c, o);
        }
        if (tid == 0) { ssum[0] = s; scnt[0] = c; }
    }
    __syncthreads();
    s = ssum[0]; c = scnt[0];
    __syncthreads();
}

__global__ void __launch_bounds__(256) sparsemax_kernel(const float* __restrict__ priors,
                                                        float* __restrict__ out) {
    __shared__ float ssum[8];
    __shared__ int scnt[8];
    const int row = blockIdx.x;
    const int vb  = row >> 8;
    const int tid = threadIdx.x;
    const int c0  = tid * 8;

    const float4* xr = reinterpret_cast<const float4*>(g_X + (size_t)row * D_OUT + c0);
    const float4* pr = reinterpret_cast<const float4*>(priors + (size_t)row * D_OUT + c0);
    const float4* sr = reinterpret_cast<const float4*>(g_scale + (size_t)vb * D_OUT + c0);
    const float4* hr = reinterpret_cast<const float4*>(g_shift + (size_t)vb * D_OUT + c0);

    float z[8];
    {
        float4 x0 = xr[0], x1 = xr[1], p0 = pr[0], p1 = pr[1];
        float4 s0 = sr[0], s1 = sr[1], h0 = hr[0], h1 = hr[1];
        z[0] = fmaf(x0.x, s0.x, h0.x) * p0.x;
        z[1] = fmaf(x0.y, s0.y, h0.y) * p0.y;
        z[2] = fmaf(x0.z, s0.z, h0.z) * p0.z;
        z[3] = fmaf(x0.w, s0.w, h0.w) * p0.w;
        z[4] = fmaf(x1.x, s1.x, h1.x) * p1.x;
        z[5] = fmaf(x1.y, s1.y, h1.y) * p1.y;
        z[6] = fmaf(x1.z, s1.z, h1.z) * p1.z;
        z[7] = fmaf(x1.w, s1.w, h1.w) * p1.w;
    }

    float s = 0.f; int c = 0;
    #pragma unroll
    for (int i = 0; i < 8; i++) s += z[i];
    block_red(s, c, ssum, scnt, tid);
    float tau = (s - 1.0f) * (1.0f / D_OUT);
    int prev = D_OUT;

    #pragma unroll 1
    for (int it = 0; it < 64; it++) {
        s = 0.f; c = 0;
        #pragma unroll
        for (int i = 0; i < 8; i++)
            if (z[i] > tau) { s += z[i]; c++; }
        block_red(s, c, ssum, scnt, tid);
        if (c == prev) break;
        tau = (s - 1.0f) / (float)c;
        prev = c;
    }

    float4 o0, o1;
    o0.x = fmaxf(z[0] - tau, 0.f); o0.y = fmaxf(z[1] - tau, 0.f);
    o0.z = fmaxf(z[2] - tau, 0.f); o0.w = fmaxf(z[3] - tau, 0.f);
    o1.x = fmaxf(z[4] - tau, 0.f); o1.y = fmaxf(z[5] - tau, 0.f);
    o1.z = fmaxf(z[6] - tau, 0.f); o1.w = fmaxf(z[7] - tau, 0.f);
    float4* op = reinterpret_cast<float4*>(out + (size_t)row * D_OUT + c0);
    op[0] = o0; op[1] = o1;
}

// -------- launch --------
extern "C" void kernel_launch(void* const* d_in, const int* in_sizes, int n_in,
                              void* d_out, int out_size) {
    (void)in_sizes; (void)n_in; (void)out_size;
    const float* priors = (const float*)d_in[0];
    const float* feat   = (const float*)d_in[1];
    const float* W      = (const float*)d_in[2];
    const float* gamma  = (const float*)d_in[3];
    const float* beta   = (const float*)d_in[4];

    cudaFuncSetAttribute(gemm_kernel, cudaFuncAttributeMaxDynamicSharedMemorySize, GEMM_SMEM);

    dummy_kernel<<<1, 32>>>();
    convertA_kernel<<<4096, 256>>>((const float4*)feat);
    convertB_kernel<<<512, 256>>>((const float4*)W);
    gemm_kernel<<<dim3(D_OUT / TN, B_ROWS / TM), 256, GEMM_SMEM>>>();
    finalize_kernel<<<dim3(D_OUT / 256, NVB), 256>>>(gamma, beta);
    sparsemax_kernel<<<B_ROWS, 256>>>(priors, (float*)d_out);
}

// round 5
// speedup vs baseline: 1.1834x; 1.0268x over previous
#include <cuda_runtime.h>
#include <cuda_bf16.h>
#include <stdint.h>

#define B_ROWS 32768
#define D_IN   512
#define D_OUT  2048
#define VBS    256
#define NVB    128
#define EPS_BN 1e-5f

// GEMM tiling (HMMA mma.sync path; tcgen05 not supported by this toolchain target)
#define TM 128
#define TN 128
#define TK 32
#define STAGES 3
#define KSTAGES (D_IN / TK)           // 16

#define TILE_B   8192                 // one 128x32 bf16 tile
#define STAGE_B  (4 * TILE_B)         // Ahi, Alo, Bhi, Blo
#define GEMM_SMEM (STAGES * STAGE_B)  // 98304 -> 2 CTAs/SM

// -------- static device scratch (no cudaMalloc allowed) --------
__device__ __align__(1024) __nv_bfloat16 g_Ahi[(size_t)B_ROWS * D_IN];
__device__ __align__(1024) __nv_bfloat16 g_Alo[(size_t)B_ROWS * D_IN];
__device__ __align__(1024) __nv_bfloat16 g_Bhi[(size_t)D_OUT * D_IN];
__device__ __align__(1024) __nv_bfloat16 g_Blo[(size_t)D_OUT * D_IN];
__device__ __align__(1024) float g_X[(size_t)B_ROWS * D_OUT];
__device__ __align__(1024) float g_sum[(size_t)NVB * D_OUT];
__device__ __align__(1024) float g_sq[(size_t)NVB * D_OUT];
__device__ __align__(1024) float g_scale[(size_t)NVB * D_OUT];
__device__ __align__(1024) float g_shift[(size_t)NVB * D_OUT];

// -------- helpers --------
__device__ __forceinline__ uint32_t cvta_shared_u32(const void* p) {
    uint32_t r;
    asm("{ .reg .u64 t; cvta.to.shared.u64 t, %1; cvt.u32.u64 %0, t; }" : "=r"(r) : "l"(p));
    return r;
}
__device__ __forceinline__ void cp16(uint32_t dst, const void* src) {
    asm volatile("cp.async.cg.shared.global [%0], [%1], 16;" :: "r"(dst), "l"(src) : "memory");
}
__device__ __forceinline__ void cp_commit() { asm volatile("cp.async.commit_group;" ::: "memory"); }
__device__ __forceinline__ void cp_wait1()  { asm volatile("cp.async.wait_group 1;" ::: "memory"); }

__device__ __forceinline__ void ldsm_x4(uint32_t& r0, uint32_t& r1, uint32_t& r2, uint32_t& r3,
                                        uint32_t addr) {
    asm volatile("ldmatrix.sync.aligned.m8n8.x4.shared.b16 {%0,%1,%2,%3}, [%4];"
                 : "=r"(r0), "=r"(r1), "=r"(r2), "=r"(r3) : "r"(addr));
}
__device__ __forceinline__ void hmma(float* c, const uint32_t* a, const uint32_t* b) {
    asm volatile("mma.sync.aligned.m16n8k16.row.col.f32.bf16.bf16.f32 "
                 "{%0,%1,%2,%3}, {%4,%5,%6,%7}, {%8,%9}, {%0,%1,%2,%3};"
                 : "+f"(c[0]), "+f"(c[1]), "+f"(c[2]), "+f"(c[3])
                 : "r"(a[0]), "r"(a[1]), "r"(a[2]), "r"(a[3]), "r"(b[0]), "r"(b[1]));
}

// swizzled smem byte offset for (row, 16B-chunk c) of a 128x32-bf16 tile (64B rows)
__device__ __forceinline__ uint32_t swoff(int row, int c) {
    return (uint32_t)(row * 64 + ((c ^ ((row >> 1) & 3)) << 4));
}

// -------- dummy (aligns ncu capture slot onto the GEMM) --------
__global__ void dummy_kernel() {}

// -------- fp32 -> bf16 hi/lo split --------
__device__ __forceinline__ void split_store(__nv_bfloat162* hi, __nv_bfloat162* lo,
                                            int i, float4 v) {
    __nv_bfloat16 h0 = __float2bfloat16(v.x), h1 = __float2bfloat16(v.y);
    __nv_bfloat16 h2 = __float2bfloat16(v.z), h3 = __float2bfloat16(v.w);
    float r0 = v.x - __bfloat162float(h0), r1 = v.y - __bfloat162float(h1);
    float r2 = v.z - __bfloat162float(h2), r3 = v.w - __bfloat162float(h3);
    hi[2*i+0] = __halves2bfloat162(h0, h1);
    hi[2*i+1] = __halves2bfloat162(h2, h3);
    lo[2*i+0] = __halves2bfloat162(__float2bfloat16(r0), __float2bfloat16(r1));
    lo[2*i+1] = __halves2bfloat162(__float2bfloat16(r2), __float2bfloat16(r3));
}
__global__ void convertA_kernel(const float4* __restrict__ src) {
    const int n4 = (B_ROWS * D_IN) / 4;
    __nv_bfloat162* hi = reinterpret_cast<__nv_bfloat162*>(g_Ahi);
    __nv_bfloat162* lo = reinterpret_cast<__nv_bfloat162*>(g_Alo);
    for (int i = blockIdx.x * blockDim.x + threadIdx.x; i < n4; i += gridDim.x * blockDim.x)
        split_store(hi, lo, i, src[i]);
}
__global__ void convertB_kernel(const float4* __restrict__ src) {
    const int n4 = (D_OUT * D_IN) / 4;
    __nv_bfloat162* hi = reinterpret_cast<__nv_bfloat162*>(g_Bhi);
    __nv_bfloat162* lo = reinterpret_cast<__nv_bfloat162*>(g_Blo);
    int gid = blockIdx.x * blockDim.x + threadIdx.x;
    for (int i = gid; i < n4; i += gridDim.x * blockDim.x)
        split_store(hi, lo, i, src[i]);
    // zero the BN partial-sum accumulators (2 x 262144 floats, 131072 threads)
    g_sum[gid] = 0.f; g_sum[gid + 131072] = 0.f;
    g_sq[gid]  = 0.f; g_sq[gid + 131072]  = 0.f;
}

// -------- GEMM: X = A(32768x512) @ B(2048x512)^T via HMMA bf16x3, fused BN partials --------
__device__ __forceinline__ void load_stage(uint32_t smem, int buf, int bm, int bn,
                                           int k0, int tid) {
    uint32_t base = smem + (uint32_t)buf * STAGE_B;
    #pragma unroll
    for (int i = 0; i < 2; i++) {
        int idx = tid + i * 256;           // 0..511 : 128 rows x 4 chunks
        int r = idx >> 2, c = idx & 3;
        uint32_t off = swoff(r, c);
        const __nv_bfloat16* ga = g_Ahi + (size_t)(bm * TM + r) * D_IN + k0 + c * 8;
        const __nv_bfloat16* gb = g_Bhi + (size_t)(bn * TN + r) * D_IN + k0 + c * 8;
        cp16(base + off,                ga);
        cp16(base + TILE_B + off,       ga + (g_Alo - g_Ahi));
        cp16(base + 2 * TILE_B + off,   gb);
        cp16(base + 3 * TILE_B + off,   gb + (g_Blo - g_Bhi));
    }
}

__global__ void __launch_bounds__(256, 2) gemm_kernel() {
    extern __shared__ char smraw[];
    const uint32_t smem = cvta_shared_u32(smraw);

    const int tid  = threadIdx.x;
    const int lane = tid & 31;
    const int wid  = tid >> 5;
    const int wm   = wid & 1;        // 2 warps along M
    const int wn   = wid >> 1;       // 4 warps along N
    const int bm = blockIdx.y, bn = blockIdx.x;

    uint32_t aOff[4], bOff[2];
    {
        int cA = lane >> 4;
        #pragma unroll
        for (int mi = 0; mi < 4; mi++)
            aOff[mi] = swoff(wm * 64 + mi * 16 + (lane & 15), cA);
        int cB = (lane >> 3) & 1;
        #pragma unroll
        for (int bi = 0; bi < 2; bi++)
            bOff[bi] = swoff(wn * 32 + bi * 16 + ((lane >> 4) << 3) + (lane & 7), cB);
    }

    float acc[4][4][4];
    #pragma unroll
    for (int mi = 0; mi < 4; mi++)
        #pragma unroll
        for (int ni = 0; ni < 4; ni++)
            #pragma unroll
            for (int k = 0; k < 4; k++) acc[mi][ni][k] = 0.f;

    load_stage(smem, 0, bm, bn, 0, tid);  cp_commit();
    load_stage(smem, 1, bm, bn, TK, tid); cp_commit();

    #pragma unroll 1
    for (int ks = 0; ks < KSTAGES; ks++) {
        cp_wait1();
        __syncthreads();   // single barrier per stage: all cp.async issues occur
                           // after this point and target buffer (ks+2)%3, whose
                           // readers all finished stage ks-1 before arriving here
        if (ks + 2 < KSTAGES)
            load_stage(smem, (ks + 2) % STAGES, bm, bn, (ks + 2) * TK, tid);
        cp_commit();

        uint32_t base = smem + (uint32_t)(ks % STAGES) * STAGE_B;

        #pragma unroll
        for (int j = 0; j < 2; j++) {
            const uint32_t jx = j << 5;
            uint32_t a[4][4], b[4][2], b2[4][2];
            #pragma unroll
            for (int mi = 0; mi < 4; mi++)
                ldsm_x4(a[mi][0], a[mi][1], a[mi][2], a[mi][3], base + (aOff[mi] ^ jx));
            #pragma unroll
            for (int bi = 0; bi < 2; bi++) {
                uint32_t bd = base + 2 * TILE_B + (bOff[bi] ^ jx);
                ldsm_x4(b[2*bi][0], b[2*bi][1], b[2*bi+1][0], b[2*bi+1][1], bd);
                ldsm_x4(b2[2*bi][0], b2[2*bi][1], b2[2*bi+1][0], b2[2*bi+1][1], bd + TILE_B);
            }
            // group 1: ahi * bhi
            #pragma unroll
            for (int mi = 0; mi < 4; mi++)
                #pragma unroll
                for (int ni = 0; ni < 4; ni++) hmma(acc[mi][ni], a[mi], b[ni]);
            // group 2: ahi * blo
            #pragma unroll
            for (int mi = 0; mi < 4; mi++)
                #pragma unroll
                for (int ni = 0; ni < 4; ni++) hmma(acc[mi][ni], a[mi], b2[ni]);
            // reload a := alo (reuse registers), group 3: alo * bhi
            #pragma unroll
            for (int mi = 0; mi < 4; mi++)
                ldsm_x4(a[mi][0], a[mi][1], a[mi][2], a[mi][3],
                        base + TILE_B + (aOff[mi] ^ jx));
            #pragma unroll
            for (int mi = 0; mi < 4; mi++)
                #pragma unroll
                for (int ni = 0; ni < 4; ni++) hmma(acc[mi][ni], a[mi], b[ni]);
        }
    }

    // epilogue: write 128x128 fp32 tile + BN column partial sums
    const int rbase = bm * TM + wm * 64 + (lane >> 2);
    const int cbase = bn * TN + wn * 32 + (lane & 3) * 2;
    #pragma unroll
    for (int mi = 0; mi < 4; mi++) {
        #pragma unroll
        for (int ni = 0; ni < 4; ni++) {
            float* p0 = g_X + (size_t)(rbase + mi * 16) * D_OUT + cbase + ni * 8;
            float* p1 = p0 + 8 * D_OUT;
            reinterpret_cast<float2*>(p0)[0] = make_float2(acc[mi][ni][0], acc[mi][ni][1]);
            reinterpret_cast<float2*>(p1)[0] = make_float2(acc[mi][ni][2], acc[mi][ni][3]);
        }
    }
    // column partials over this warp's 64 rows
    const int vb = bm >> 1;
    #pragma unroll
    for (int ni = 0; ni < 4; ni++) {
        #pragma unroll
        for (int sc = 0; sc < 2; sc++) {
            float s = 0.f, q = 0.f;
            #pragma unroll
            for (int mi = 0; mi < 4; mi++) {
                float v0 = acc[mi][ni][sc], v1 = acc[mi][ni][sc + 2];
                s += v0 + v1;
                q = fmaf(v0, v0, q); q = fmaf(v1, v1, q);
            }
            #pragma unroll
            for (int off = 4; off < 32; off <<= 1) {
                s += __shfl_xor_sync(0xFFFFFFFFu, s, off);
                q += __shfl_xor_sync(0xFFFFFFFFu, q, off);
            }
            if ((lane >> 2) == 0) {
                int col = cbase + ni * 8 + sc;
                atomicAdd(&g_sum[(size_t)vb * D_OUT + col], s);
                atomicAdd(&g_sq[(size_t)vb * D_OUT + col], q);
            }
        }
    }
}

// -------- BN finalize: sums -> scale/shift --------
__global__ void finalize_kernel(const float* __restrict__ gamma, const float* __restrict__ beta) {
    const int col = blockIdx.x * 256 + threadIdx.x;
    const int vb  = blockIdx.y;
    const size_t i = (size_t)vb * D_OUT + col;
    float mean = g_sum[i] * (1.0f / VBS);
    float var  = fmaxf(g_sq[i] * (1.0f / VBS) - mean * mean, 0.f);
    float sc   = gamma[col] * rsqrtf(var + EPS_BN);
    g_scale[i] = sc;
    g_shift[i] = beta[col] - mean * sc;
}

// -------- fused BN-apply * priors + sparsemax (Michelot, 1 barrier/iter) --------
__global__ void __launch_bounds__(256) sparsemax_kernel(const float* __restrict__ priors,
                                                        float* __restrict__ out) {
    __shared__ float ssum[2][8];
    __shared__ float scnt[2][8];
    const int row = blockIdx.x;
    const int vb  = row >> 8;
    const int tid = threadIdx.x;
    const int wrp = tid >> 5;
    const int lane = tid & 31;
    const int c0  = tid * 8;

    const float4* xr = reinterpret_cast<const float4*>(g_X + (size_t)row * D_OUT + c0);
    const float4* pr = reinterpret_cast<const float4*>(priors + (size_t)row * D_OUT + c0);
    const float4* sr = reinterpret_cast<const float4*>(g_scale + (size_t)vb * D_OUT + c0);
    const float4* hr = reinterpret_cast<const float4*>(g_shift + (size_t)vb * D_OUT + c0);

    float z[8];
    {
        float4 x0 = xr[0], x1 = xr[1], p0 = pr[0], p1 = pr[1];
        float4 s0 = sr[0], s1 = sr[1], h0 = hr[0], h1 = hr[1];
        z[0] = fmaf(x0.x, s0.x, h0.x) * p0.x;
        z[1] = fmaf(x0.y, s0.y, h0.y) * p0.y;
        z[2] = fmaf(x0.z, s0.z, h0.z) * p0.z;
        z[3] = fmaf(x0.w, s0.w, h0.w) * p0.w;
        z[4] = fmaf(x1.x, s1.x, h1.x) * p1.x;
        z[5] = fmaf(x1.y, s1.y, h1.y) * p1.y;
        z[6] = fmaf(x1.z, s1.z, h1.z) * p1.z;
        z[7] = fmaf(x1.w, s1.w, h1.w) * p1.w;
    }

    // iteration 0: full sum
    float s = ((z[0] + z[1]) + (z[2] + z[3])) + ((z[4] + z[5]) + (z[6] + z[7]));
    #pragma unroll
    for (int o = 16; o; o >>= 1) s += __shfl_xor_sync(0xFFFFFFFFu, s, o);
    if (lane == 0) ssum[0][wrp] = s;
    __syncthreads();
    s = ((ssum[0][0] + ssum[0][1]) + (ssum[0][2] + ssum[0][3]))
      + ((ssum[0][4] + ssum[0][5]) + (ssum[0][6] + ssum[0][7]));
    float tau  = (s - 1.0f) * (1.0f / D_OUT);
    float prev = (float)D_OUT;

    #pragma unroll 1
    for (int it = 1; it < 64; it++) {
        const int p = it & 1;
        float ls = 0.f, lc = 0.f;
        #pragma unroll
        for (int i = 0; i < 8; i++)
            if (z[i] > tau) { ls += z[i]; lc += 1.0f; }
        #pragma unroll
        for (int o = 16; o; o >>= 1) {
            ls += __shfl_xor_sync(0xFFFFFFFFu, ls, o);
            lc += __shfl_xor_sync(0xFFFFFFFFu, lc, o);
        }
        if (lane == 0) { ssum[p][wrp] = ls; scnt[p][wrp] = lc; }
        __syncthreads();
        ls = ((ssum[p][0] + ssum[p][1]) + (ssum[p][2] + ssum[p][3]))
           + ((ssum[p][4] + ssum[p][5]) + (ssum[p][6] + ssum[p][7]));
        lc = ((scnt[p][0] + scnt[p][1]) + (scnt[p][2] + scnt[p][3]))
           + ((scnt[p][4] + scnt[p][5]) + (scnt[p][6] + scnt[p][7]));
        if (lc == prev) break;
        tau  = (ls - 1.0f) / lc;
        prev = lc;
    }

    float4 o0, o1;
    o0.x = fmaxf(z[0] - tau, 0.f); o0.y = fmaxf(z[1] - tau, 0.f);
    o0.z = fmaxf(z[2] - tau, 0.f); o0.w = fmaxf(z[3] - tau, 0.f);
    o1.x = fmaxf(z[4] - tau, 0.f); o1.y = fmaxf(z[5] - tau, 0.f);
    o1.z = fmaxf(z[6] - tau, 0.f); o1.w = fmaxf(z[7] - tau, 0.f);
    float4* op = reinterpret_cast<float4*>(out + (size_t)row * D_OUT + c0);
    op[0] = o0; op[1] = o1;
}

// -------- launch --------
extern "C" void kernel_launch(void* const* d_in, const int* in_sizes, int n_in,
                              void* d_out, int out_size) {
    (void)in_sizes; (void)n_in; (void)out_size;
    const float* priors = (const float*)d_in[0];
    const float* feat   = (const float*)d_in[1];
    const float* W      = (const float*)d_in[2];
    const float* gamma  = (const float*)d_in[3];
    const float* beta   = (const float*)d_in[4];

    cudaFuncSetAttribute(gemm_kernel, cudaFuncAttributeMaxDynamicSharedMemorySize, GEMM_SMEM);

    dummy_kernel<<<1, 32>>>();
    convertA_kernel<<<4096, 256>>>((const float4*)feat);
    convertB_kernel<<<512, 256>>>((const float4*)W);
    gemm_kernel<<<dim3(D_OUT / TN, B_ROWS / TM), 256, GEMM_SMEM>>>();
    finalize_kernel<<<dim3(D_OUT / 256, NVB), 256>>>(gamma, beta);
    sparsemax_kernel<<<B_ROWS, 256>>>(priors, (float*)d_out);
}

// round 6
// speedup vs baseline: 1.7704x; 1.4960x over previous
#include <cuda_runtime.h>
#include <cuda_fp16.h>
#include <stdint.h>

#define B_ROWS 32768
#define D_IN   512
#define D_OUT  2048
#define VBS    256
#define NVB    128
#define EPS_BN 1e-5f

// GEMM tiling (HMMA mma.sync fp16x2 path)
#define TM 128
#define TN 128
#define TK 32
#define STAGES 4
#define KSTAGES (D_IN / TK)           // 16

#define TILE_B   8192                 // one 128x32 fp16 tile
#define STAGE_B  (3 * TILE_B)         // Ah, Al, Bh
#define GEMM_SMEM (STAGES * STAGE_B)  // 98304 -> 2 CTAs/SM

// -------- static device scratch (no cudaMalloc allowed) --------
__device__ __align__(1024) __half g_Ah[(size_t)B_ROWS * D_IN];
__device__ __align__(1024) __half g_Al[(size_t)B_ROWS * D_IN];
__device__ __align__(1024) __half g_Bh[(size_t)D_OUT * D_IN];
__device__ __align__(1024) float g_X[(size_t)B_ROWS * D_OUT];
__device__ __align__(1024) float g_sum[(size_t)NVB * D_OUT];
__device__ __align__(1024) float g_sq[(size_t)NVB * D_OUT];
__device__ __align__(1024) float g_scale[(size_t)NVB * D_OUT];
__device__ __align__(1024) float g_shift[(size_t)NVB * D_OUT];

// -------- helpers --------
__device__ __forceinline__ uint32_t cvta_shared_u32(const void* p) {
    uint32_t r;
    asm("{ .reg .u64 t; cvta.to.shared.u64 t, %1; cvt.u32.u64 %0, t; }" : "=r"(r) : "l"(p));
    return r;
}
__device__ __forceinline__ void cp16(uint32_t dst, const void* src) {
    asm volatile("cp.async.cg.shared.global [%0], [%1], 16;" :: "r"(dst), "l"(src) : "memory");
}
__device__ __forceinline__ void cp_commit() { asm volatile("cp.async.commit_group;" ::: "memory"); }
__device__ __forceinline__ void cp_wait2()  { asm volatile("cp.async.wait_group 2;" ::: "memory"); }

__device__ __forceinline__ void ldsm_x4(uint32_t& r0, uint32_t& r1, uint32_t& r2, uint32_t& r3,
                                        uint32_t addr) {
    asm volatile("ldmatrix.sync.aligned.m8n8.x4.shared.b16 {%0,%1,%2,%3}, [%4];"
                 : "=r"(r0), "=r"(r1), "=r"(r2), "=r"(r3) : "r"(addr));
}
__device__ __forceinline__ void hmma(float* c, const uint32_t* a, const uint32_t* b) {
    asm volatile("mma.sync.aligned.m16n8k16.row.col.f32.f16.f16.f32 "
                 "{%0,%1,%2,%3}, {%4,%5,%6,%7}, {%8,%9}, {%0,%1,%2,%3};"
                 : "+f"(c[0]), "+f"(c[1]), "+f"(c[2]), "+f"(c[3])
                 : "r"(a[0]), "r"(a[1]), "r"(a[2]), "r"(a[3]), "r"(b[0]), "r"(b[1]));
}

// swizzled smem byte offset for (row, 16B-chunk c) of a 128x32-fp16 tile (64B rows)
__device__ __forceinline__ uint32_t swoff(int row, int c) {
    return (uint32_t)(row * 64 + ((c ^ ((row >> 1) & 3)) << 4));
}

// -------- dummy (keeps GEMM in the ncu capture slot) --------
__global__ void dummy_kernel() {}

// -------- fp32 -> fp16 hi/lo split (A) / fp16 round (B) --------
__global__ void convertA_kernel(const float4* __restrict__ src) {
    const int n4 = (B_ROWS * D_IN) / 4;
    __half2* hi = reinterpret_cast<__half2*>(g_Ah);
    __half2* lo = reinterpret_cast<__half2*>(g_Al);
    for (int i = blockIdx.x * blockDim.x + threadIdx.x; i < n4; i += gridDim.x * blockDim.x) {
        float4 v = src[i];
        __half h0 = __float2half(v.x), h1 = __float2half(v.y);
        __half h2 = __float2half(v.z), h3 = __float2half(v.w);
        float r0 = v.x - __half2float(h0), r1 = v.y - __half2float(h1);
        float r2 = v.z - __half2float(h2), r3 = v.w - __half2float(h3);
        hi[2*i+0] = __halves2half2(h0, h1);
        hi[2*i+1] = __halves2half2(h2, h3);
        lo[2*i+0] = __halves2half2(__float2half(r0), __float2half(r1));
        lo[2*i+1] = __halves2half2(__float2half(r2), __float2half(r3));
    }
}
__global__ void convertB_kernel(const float4* __restrict__ src) {
    const int n4 = (D_OUT * D_IN) / 4;
    __half2* hi = reinterpret_cast<__half2*>(g_Bh);
    int gid = blockIdx.x * blockDim.x + threadIdx.x;
    for (int i = gid; i < n4; i += gridDim.x * blockDim.x) {
        float4 v = src[i];
        hi[2*i+0] = __halves2half2(__float2half(v.x), __float2half(v.y));
        hi[2*i+1] = __halves2half2(__float2half(v.z), __float2half(v.w));
    }
    // zero the BN partial-sum accumulators (2 x 262144 floats, 131072 threads)
    g_sum[gid] = 0.f; g_sum[gid + 131072] = 0.f;
    g_sq[gid]  = 0.f; g_sq[gid + 131072]  = 0.f;
}

// -------- GEMM: X = A(32768x512) @ B(2048x512)^T via HMMA fp16x2, fused BN partials ----
__device__ __forceinline__ void load_stage(uint32_t smem, int buf, int bm, int bn,
                                           int k0, int tid) {
    uint32_t base = smem + (uint32_t)buf * STAGE_B;
    #pragma unroll
    for (int i = 0; i < 2; i++) {
        int idx = tid + i * 256;           // 0..511 : 128 rows x 4 chunks
        int r = idx >> 2, c = idx & 3;
        uint32_t off = swoff(r, c);
        const __half* ga = g_Ah + (size_t)(bm * TM + r) * D_IN + k0 + c * 8;
        const __half* gb = g_Bh + (size_t)(bn * TN + r) * D_IN + k0 + c * 8;
        cp16(base + off,              ga);
        cp16(base + TILE_B + off,     ga + (g_Al - g_Ah));
        cp16(base + 2 * TILE_B + off, gb);
    }
}

__global__ void __launch_bounds__(256, 2) gemm_kernel() {
    extern __shared__ char smraw[];
    const uint32_t smem = cvta_shared_u32(smraw);

    const int tid  = threadIdx.x;
    const int lane = tid & 31;
    const int wid  = tid >> 5;
    const int wm   = wid & 1;        // 2 warps along M
    const int wn   = wid >> 1;       // 4 warps along N
    const int bm = blockIdx.y, bn = blockIdx.x;

    uint32_t aOff[4], bOff[2];
    {
        int cA = lane >> 4;
        #pragma unroll
        for (int mi = 0; mi < 4; mi++)
            aOff[mi] = swoff(wm * 64 + mi * 16 + (lane & 15), cA);
        int cB = (lane >> 3) & 1;
        #pragma unroll
        for (int bi = 0; bi < 2; bi++)
            bOff[bi] = swoff(wn * 32 + bi * 16 + ((lane >> 4) << 3) + (lane & 7), cB);
    }

    float acc[4][4][4];
    #pragma unroll
    for (int mi = 0; mi < 4; mi++)
        #pragma unroll
        for (int ni = 0; ni < 4; ni++)
            #pragma unroll
            for (int k = 0; k < 4; k++) acc[mi][ni][k] = 0.f;

    load_stage(smem, 0, bm, bn, 0, tid);      cp_commit();
    load_stage(smem, 1, bm, bn, TK, tid);     cp_commit();
    load_stage(smem, 2, bm, bn, 2 * TK, tid); cp_commit();

    #pragma unroll 1
    for (int ks = 0; ks < KSTAGES; ks++) {
        cp_wait2();
        __syncthreads();
        if (ks + 3 < KSTAGES)
            load_stage(smem, (ks + 3) & 3, bm, bn, (ks + 3) * TK, tid);
        cp_commit();

        uint32_t base = smem + (uint32_t)(ks & 3) * STAGE_B;

        #pragma unroll
        for (int j = 0; j < 2; j++) {
            const uint32_t jx = j << 5;
            uint32_t a[4][4], b[4][2];
            #pragma unroll
            for (int mi = 0; mi < 4; mi++)
                ldsm_x4(a[mi][0], a[mi][1], a[mi][2], a[mi][3], base + (aOff[mi] ^ jx));
            #pragma unroll
            for (int bi = 0; bi < 2; bi++) {
                uint32_t bd = base + 2 * TILE_B + (bOff[bi] ^ jx);
                ldsm_x4(b[2*bi][0], b[2*bi][1], b[2*bi+1][0], b[2*bi+1][1], bd);
            }
            // group 1: ah * bh
            #pragma unroll
            for (int mi = 0; mi < 4; mi++)
                #pragma unroll
                for (int ni = 0; ni < 4; ni++) hmma(acc[mi][ni], a[mi], b[ni]);
            // reload a := al, group 2: al * bh
            #pragma unroll
            for (int mi = 0; mi < 4; mi++)
                ldsm_x4(a[mi][0], a[mi][1], a[mi][2], a[mi][3],
                        base + TILE_B + (aOff[mi] ^ jx));
            #pragma unroll
            for (int mi = 0; mi < 4; mi++)
                #pragma unroll
                for (int ni = 0; ni < 4; ni++) hmma(acc[mi][ni], a[mi], b[ni]);
        }
    }

    // epilogue: write 128x128 fp32 tile + BN column partial sums
    const int rbase = bm * TM + wm * 64 + (lane >> 2);
    const int cbase = bn * TN + wn * 32 + (lane & 3) * 2;
    #pragma unroll
    for (int mi = 0; mi < 4; mi++) {
        #pragma unroll
        for (int ni = 0; ni < 4; ni++) {
            float* p0 = g_X + (size_t)(rbase + mi * 16) * D_OUT + cbase + ni * 8;
            float* p1 = p0 + 8 * D_OUT;
            reinterpret_cast<float2*>(p0)[0] = make_float2(acc[mi][ni][0], acc[mi][ni][1]);
            reinterpret_cast<float2*>(p1)[0] = make_float2(acc[mi][ni][2], acc[mi][ni][3]);
        }
    }
    const int vb = bm >> 1;
    #pragma unroll
    for (int ni = 0; ni < 4; ni++) {
        #pragma unroll
        for (int sc = 0; sc < 2; sc++) {
            float s = 0.f, q = 0.f;
            #pragma unroll
            for (int mi = 0; mi < 4; mi++) {
                float v0 = acc[mi][ni][sc], v1 = acc[mi][ni][sc + 2];
                s += v0 + v1;
                q = fmaf(v0, v0, q); q = fmaf(v1, v1, q);
            }
            #pragma unroll
            for (int off = 4; off < 32; off <<= 1) {
                s += __shfl_xor_sync(0xFFFFFFFFu, s, off);
                q += __shfl_xor_sync(0xFFFFFFFFu, q, off);
            }
            if ((lane >> 2) == 0) {
                int col = cbase + ni * 8 + sc;
                atomicAdd(&g_sum[(size_t)vb * D_OUT + col], s);
                atomicAdd(&g_sq[(size_t)vb * D_OUT + col], q);
            }
        }
    }
}

// -------- BN finalize: sums -> scale/shift --------
__global__ void finalize_kernel(const float* __restrict__ gamma, const float* __restrict__ beta) {
    const int col = blockIdx.x * 256 + threadIdx.x;
    const int vb  = blockIdx.y;
    const size_t i = (size_t)vb * D_OUT + col;
    float mean = g_sum[i] * (1.0f / VBS);
    float var  = fmaxf(g_sq[i] * (1.0f / VBS) - mean * mean, 0.f);
    float sc   = gamma[col] * rsqrtf(var + EPS_BN);
    g_scale[i] = sc;
    g_shift[i] = beta[col] - mean * sc;
}

// -------- fused BN-apply * priors + sparsemax: one warp per row, zero barriers ------
__global__ void __launch_bounds__(256, 2) sparsemax_kernel(const float* __restrict__ priors,
                                                           float* __restrict__ out) {
    const int row  = blockIdx.x * 8 + (threadIdx.x >> 5);
    const int lane = threadIdx.x & 31;
    const int vb   = row >> 8;

    const float4* xr = reinterpret_cast<const float4*>(g_X + (size_t)row * D_OUT);
    const float4* pr = reinterpret_cast<const float4*>(priors + (size_t)row * D_OUT);
    const float4* sr = reinterpret_cast<const float4*>(g_scale + (size_t)vb * D_OUT);
    const float4* hr = reinterpret_cast<const float4*>(g_shift + (size_t)vb * D_OUT);

    float z[64];
    float s = 0.f;
    #pragma unroll
    for (int c = 0; c < 16; c++) {
        const int idx = c * 32 + lane;
        float4 x = xr[idx], p = pr[idx], sc = sr[idx], sh = hr[idx];
        float z0 = fmaf(x.x, sc.x, sh.x) * p.x;
        float z1 = fmaf(x.y, sc.y, sh.y) * p.y;
        float z2 = fmaf(x.z, sc.z, sh.z) * p.z;
        float z3 = fmaf(x.w, sc.w, sh.w) * p.w;
        z[4*c+0] = z0; z[4*c+1] = z1; z[4*c+2] = z2; z[4*c+3] = z3;
        s += (z0 + z1) + (z2 + z3);
    }
    #pragma unroll
    for (int o = 16; o; o >>= 1) s += __shfl_xor_sync(0xFFFFFFFFu, s, o);

    // Michelot fixed point: tau = (sum_{z>tau} z - 1)/count (exact sparsemax threshold)
    float tau  = (s - 1.0f) * (1.0f / D_OUT);
    float prev = (float)D_OUT;
    #pragma unroll 1
    for (int it = 0; it < 64; it++) {
        float ls = 0.f, lc = 0.f;
        #pragma unroll
        for (int i = 0; i < 64; i++)
            if (z[i] > tau) { ls += z[i]; lc += 1.0f; }
        #pragma unroll
        for (int o = 16; o; o >>= 1) {
            ls += __shfl_xor_sync(0xFFFFFFFFu, ls, o);
            lc += __shfl_xor_sync(0xFFFFFFFFu, lc, o);
        }
        if (lc == prev) break;
        tau  = (ls - 1.0f) / lc;
        prev = lc;
    }

    float4* op = reinterpret_cast<float4*>(out + (size_t)row * D_OUT);
    #pragma unroll
    for (int c = 0; c < 16; c++) {
        float4 o4;
        o4.x = fmaxf(z[4*c+0] - tau, 0.f);
        o4.y = fmaxf(z[4*c+1] - tau, 0.f);
        o4.z = fmaxf(z[4*c+2] - tau, 0.f);
        o4.w = fmaxf(z[4*c+3] - tau, 0.f);
        op[c * 32 + lane] = o4;
    }
}

// -------- launch --------
extern "C" void kernel_launch(void* const* d_in, const int* in_sizes, int n_in,
                              void* d_out, int out_size) {
    (void)in_sizes; (void)n_in; (void)out_size;
    const float* priors = (const float*)d_in[0];
    const float* feat   = (const float*)d_in[1];
    const float* W      = (const float*)d_in[2];
    const float* gamma  = (const float*)d_in[3];
    const float* beta   = (const float*)d_in[4];

    cudaFuncSetAttribute(gemm_kernel, cudaFuncAttributeMaxDynamicSharedMemorySize, GEMM_SMEM);

    dummy_kernel<<<1, 32>>>();
    convertA_kernel<<<4096, 256>>>((const float4*)feat);
    convertB_kernel<<<512, 256>>>((const float4*)W);
    gemm_kernel<<<dim3(D_OUT / TN, B_ROWS / TM), 256, GEMM_SMEM>>>();
    finalize_kernel<<<dim3(D_OUT / 256, NVB), 256>>>(gamma, beta);
    sparsemax_kernel<<<B_ROWS / 8, 256>>>(priors, (float*)d_out);
}